// round 1
// baseline (speedup 1.0000x reference)
#include <cuda_runtime.h>
#include <cstddef>

#define BATCH 256
#define H 100
#define NIN 784
#define T 2500
#define BH (BATCH * H)                 // 25600
#define SEC ((size_t)T * (size_t)BH)   // 64,000,000 elements per output section

// Scratch for cur1 = x @ W1^T + b1  (no cudaMalloc allowed)
__device__ float g_cur1[BH];

// ---------------------------------------------------------------------------
// Kernel 1: cur1[b,h] = dot(x[b,:], W1[h,:]) + b1[h]
// One block per batch row b. x row staged in smem; each thread streams one
// W1 row with float4 loads (W1 = 313KB -> L2 resident, reused by 256 blocks).
// ---------------------------------------------------------------------------
__global__ void gemm_kernel(const float* __restrict__ x,
                            const float* __restrict__ W1,
                            const float* __restrict__ b1) {
    __shared__ float xs[NIN];
    const int b = blockIdx.x;
    for (int k = threadIdx.x; k < NIN; k += blockDim.x)
        xs[k] = x[b * NIN + k];
    __syncthreads();

    const int h = threadIdx.x;
    if (h < H) {
        const float4* w = reinterpret_cast<const float4*>(W1 + (size_t)h * NIN);
        float acc = 0.0f;
#pragma unroll 4
        for (int k4 = 0; k4 < NIN / 4; k4++) {
            float4 wv = w[k4];
            acc += xs[4 * k4 + 0] * wv.x;
            acc += xs[4 * k4 + 1] * wv.y;
            acc += xs[4 * k4 + 2] * wv.z;
            acc += xs[4 * k4 + 3] * wv.w;
        }
        g_cur1[b * H + h] = acc + b1[h];
    }
}

// ---------------------------------------------------------------------------
// Kernel 2: broadcast cur1 into cur_rec section (section index 2).
// One block per timestep; float4 coalesced stores; cur1 stays in L1/L2.
// ---------------------------------------------------------------------------
__global__ void cur_kernel(float* __restrict__ out) {
    const float4* c = reinterpret_cast<const float4*>(g_cur1);
    float4* o = reinterpret_cast<float4*>(out + 2 * SEC);
    const size_t base = (size_t)blockIdx.x * (BH / 4);
    for (int i = threadIdx.x; i < BH / 4; i += blockDim.x)
        o[base + i] = c[i];
}

// ---------------------------------------------------------------------------
// Kernel 3: the 2500-step LIF recurrence. One thread per (b,h) cell.
// Writes spk2 (sec 0), mem2 (sec 1), spk1 (sec 3), mem1 (sec 4).
// Consecutive tids -> contiguous addresses per section per step (coalesced).
// ---------------------------------------------------------------------------
__global__ void snn_kernel(const float* __restrict__ alpha1,
                           const float* __restrict__ beta1,
                           float* __restrict__ out) {
    const int tid = blockIdx.x * blockDim.x + threadIdx.x;
    if (tid >= BH) return;

    const float a1  = fminf(fmaxf(alpha1[0], 0.0f), 1.0f);
    const float be1 = fminf(fmaxf(beta1[0], 0.0f), 1.0f);
    const float cur = g_cur1[tid];

    float syn1 = 0.0f, mem1 = 0.0f, syn2 = 0.0f, mem2 = 0.0f;

    float* __restrict__ spk2o = out;
    float* __restrict__ mem2o = out + SEC;
    float* __restrict__ spk1o = out + 3 * SEC;
    float* __restrict__ mem1o = out + 4 * SEC;

    size_t off = (size_t)tid;
    for (int t = 0; t < T; t++, off += BH) {
        // lif1 (Synaptic, reset='zero'): reset from PREVIOUS mem
        const float keep1 = (mem1 > 1.0f) ? 0.0f : 1.0f;   // (1 - reset1)
        syn1 = a1 * syn1 + cur;
        mem1 = (be1 * mem1 + syn1) * keep1;
        const float spk1 = (mem1 > 1.0f) ? 1.0f : 0.0f;

        // lif2: fixed alpha=0.8, beta=0.9
        const float keep2 = (mem2 > 1.0f) ? 0.0f : 1.0f;
        syn2 = 0.8f * syn2 + spk1;
        mem2 = (0.9f * mem2 + syn2) * keep2;
        const float spk2 = (mem2 > 1.0f) ? 1.0f : 0.0f;

        spk2o[off] = spk2;
        mem2o[off] = mem2;
        spk1o[off] = spk1;
        mem1o[off] = mem1;
    }
}

// ---------------------------------------------------------------------------
// Inputs (metadata order): x[256*784] f32, W1[100*784] f32, b1[100] f32,
//                          alpha1[1] f32, beta1[1] f32
// Output: 5 sections of [T,B,H] f32: spk2, mem2, cur, spk1, mem1
// ---------------------------------------------------------------------------
extern "C" void kernel_launch(void* const* d_in, const int* in_sizes, int n_in,
                              void* d_out, int out_size) {
    const float* x      = (const float*)d_in[0];
    const float* W1     = (const float*)d_in[1];
    const float* b1     = (const float*)d_in[2];
    const float* alpha1 = (const float*)d_in[3];
    const float* beta1  = (const float*)d_in[4];
    float* out = (float*)d_out;

    gemm_kernel<<<BATCH, 128>>>(x, W1, b1);
    cur_kernel<<<T, 256>>>(out);
    snn_kernel<<<BH / 128, 128>>>(alpha1, beta1, out);
}

// round 2
// speedup vs baseline: 1.1263x; 1.1263x over previous
#include <cuda_runtime.h>
#include <cstddef>

#define BATCH 256
#define H 100
#define NIN 784
#define T 2500
#define BH (BATCH * H)                 // 25600
#define SEC ((size_t)T * (size_t)BH)   // 64,000,000 elements per section
#define NCHUNK 25
#define CHUNK 100                      // NCHUNK * CHUNK == T

// Scratch (no cudaMalloc allowed): cur1 and per-chunk state checkpoints
__device__ float  g_cur1[BH];
__device__ float4 g_ckpt[NCHUNK * BH];   // (syn1, mem1, syn2, mem2) at chunk start

// ---------------------------------------------------------------------------
// Shared step function — MUST be identical in phase1 and phase2 so that
// replay from checkpoints is bit-identical to a monolithic run.
// ---------------------------------------------------------------------------
__device__ __forceinline__ void lif_step(const float a1, const float be1,
                                         const float cur,
                                         float& syn1, float& mem1,
                                         float& syn2, float& mem2,
                                         float& spk1, float& spk2) {
    // lif1 (Synaptic, reset='zero'): reset from PREVIOUS mem
    const float keep1 = (mem1 > 1.0f) ? 0.0f : 1.0f;
    syn1 = fmaf(a1, syn1, cur);
    mem1 = fmaf(be1, mem1, syn1) * keep1;
    spk1 = (mem1 > 1.0f) ? 1.0f : 0.0f;
    // lif2: fixed alpha=0.8, beta=0.9
    const float keep2 = (mem2 > 1.0f) ? 0.0f : 1.0f;
    syn2 = fmaf(0.8f, syn2, spk1);
    mem2 = fmaf(0.9f, mem2, syn2) * keep2;
    spk2 = (mem2 > 1.0f) ? 1.0f : 0.0f;
}

// ---------------------------------------------------------------------------
// Kernel 1: cur1[b,h] = dot(x[b,:], W1[h,:]) + b1[h]
// One block per batch row, 700 threads: 7 K-partials (112 floats = 28 float4
// each) per output h, reduced through smem. 8x shorter latency chain than R1.
// ---------------------------------------------------------------------------
#define KSPLIT 7
#define KPART (NIN / KSPLIT)           // 112 floats = 28 float4

__global__ void gemm_kernel(const float* __restrict__ x,
                            const float* __restrict__ W1,
                            const float* __restrict__ b1) {
    __shared__ float xs[NIN];
    __shared__ float partial[H][KSPLIT + 1];   // +1 pad vs bank conflicts
    const int b = blockIdx.x;
    const int tid = threadIdx.x;

    for (int k = tid; k < NIN; k += blockDim.x)
        xs[k] = x[b * NIN + k];
    __syncthreads();

    if (tid < H * KSPLIT) {
        const int h = tid % H;
        const int p = tid / H;
        const float4* w = reinterpret_cast<const float4*>(W1 + (size_t)h * NIN + p * KPART);
        const float* xp = xs + p * KPART;
        float acc = 0.0f;
#pragma unroll
        for (int k4 = 0; k4 < KPART / 4; k4++) {
            float4 wv = w[k4];
            acc = fmaf(xp[4 * k4 + 0], wv.x, acc);
            acc = fmaf(xp[4 * k4 + 1], wv.y, acc);
            acc = fmaf(xp[4 * k4 + 2], wv.z, acc);
            acc = fmaf(xp[4 * k4 + 3], wv.w, acc);
        }
        partial[h][p] = acc;
    }
    __syncthreads();

    if (tid < H) {
        float s = b1[tid];
#pragma unroll
        for (int p = 0; p < KSPLIT; p++) s += partial[tid][p];
        g_cur1[b * H + tid] = s;
    }
}

// ---------------------------------------------------------------------------
// Kernel 2 (phase 1): run full recurrence, store ONLY state checkpoints at the
// start of each chunk. Compute-only; no bulk output traffic.
// ---------------------------------------------------------------------------
__global__ void snn_phase1(const float* __restrict__ alpha1,
                           const float* __restrict__ beta1) {
    const int cell = blockIdx.x * blockDim.x + threadIdx.x;
    if (cell >= BH) return;

    const float a1  = fminf(fmaxf(alpha1[0], 0.0f), 1.0f);
    const float be1 = fminf(fmaxf(beta1[0], 0.0f), 1.0f);
    const float cur = g_cur1[cell];

    float syn1 = 0.0f, mem1 = 0.0f, syn2 = 0.0f, mem2 = 0.0f;
    float spk1, spk2;

    for (int c = 0; c < NCHUNK; c++) {
        g_ckpt[c * BH + cell] = make_float4(syn1, mem1, syn2, mem2);
#pragma unroll 5
        for (int i = 0; i < CHUNK; i++)
            lif_step(a1, be1, cur, syn1, mem1, syn2, mem2, spk1, spk2);
    }
}

// ---------------------------------------------------------------------------
// Kernel 3 (phase 2): 25x parallelism over time chunks. Each thread replays
// CHUNK steps from its checkpoint and writes all 5 output sections
// (cur broadcast fused here). 640k threads -> store-side DRAM saturation.
// ---------------------------------------------------------------------------
__global__ void snn_phase2(const float* __restrict__ alpha1,
                           const float* __restrict__ beta1,
                           float* __restrict__ out) {
    const int cell = blockIdx.x * blockDim.x + threadIdx.x;
    const int c = blockIdx.y;

    const float a1  = fminf(fmaxf(alpha1[0], 0.0f), 1.0f);
    const float be1 = fminf(fmaxf(beta1[0], 0.0f), 1.0f);
    const float cur = g_cur1[cell];

    const float4 st = g_ckpt[c * BH + cell];
    float syn1 = st.x, mem1 = st.y, syn2 = st.z, mem2 = st.w;
    float spk1, spk2;

    float* __restrict__ spk2o = out;
    float* __restrict__ mem2o = out + SEC;
    float* __restrict__ curo  = out + 2 * SEC;
    float* __restrict__ spk1o = out + 3 * SEC;
    float* __restrict__ mem1o = out + 4 * SEC;

    size_t off = (size_t)(c * CHUNK) * BH + cell;
#pragma unroll 4
    for (int i = 0; i < CHUNK; i++, off += BH) {
        lif_step(a1, be1, cur, syn1, mem1, syn2, mem2, spk1, spk2);
        spk2o[off] = spk2;
        mem2o[off] = mem2;
        curo[off]  = cur;
        spk1o[off] = spk1;
        mem1o[off] = mem1;
    }
}

// ---------------------------------------------------------------------------
// Inputs: x[256*784], W1[100*784], b1[100], alpha1[1], beta1[1]  (all f32)
// Output: 5 sections of [T,B,H] f32: spk2, mem2, cur, spk1, mem1
// ---------------------------------------------------------------------------
extern "C" void kernel_launch(void* const* d_in, const int* in_sizes, int n_in,
                              void* d_out, int out_size) {
    const float* x      = (const float*)d_in[0];
    const float* W1     = (const float*)d_in[1];
    const float* b1     = (const float*)d_in[2];
    const float* alpha1 = (const float*)d_in[3];
    const float* beta1  = (const float*)d_in[4];
    float* out = (float*)d_out;

    gemm_kernel<<<BATCH, H * KSPLIT>>>(x, W1, b1);
    snn_phase1<<<BH / 128, 128>>>(alpha1, beta1);
    dim3 grid2(BH / 128, NCHUNK);
    snn_phase2<<<grid2, 128>>>(alpha1, beta1, out);
}

// round 3
// speedup vs baseline: 1.1867x; 1.0536x over previous
#include <cuda_runtime.h>
#include <cstddef>

#define BATCH 256
#define H 100
#define NIN 784
#define T 2500
#define BH (BATCH * H)                 // 25600
#define SEC ((size_t)T * (size_t)BH)   // 64,000,000 elements per section
#define NCHUNK 25
#define CHUNK 100                      // NCHUNK * CHUNK == T

#define P1_BLOCKS (BH / 128)           // 200 phase-1 blocks (1 cell/thread)
#define CELLS_PER_THREAD 4
#define P2_BLOCKS_PER_CHUNK (BH / (128 * CELLS_PER_THREAD))   // 50
#define P2_BLOCKS (NCHUNK * P2_BLOCKS_PER_CHUNK)              // 1250

// Scratch (no cudaMalloc allowed)
__device__ float  g_cur1[BH];
__device__ float4 g_ckpt[NCHUNK * BH];        // state at start of each chunk
__device__ int    g_flags[NCHUNK * 32];       // 1 flag per chunk, 128B apart

// ---------------------------------------------------------------------------
// Shared step function — identical in phase1/phase2 so replay from checkpoints
// is bit-identical to a monolithic run.
// ---------------------------------------------------------------------------
__device__ __forceinline__ void lif_step(const float a1, const float be1,
                                         const float cur,
                                         float& syn1, float& mem1,
                                         float& syn2, float& mem2,
                                         float& spk1, float& spk2) {
    const float keep1 = (mem1 > 1.0f) ? 0.0f : 1.0f;   // reset from PREVIOUS mem
    syn1 = fmaf(a1, syn1, cur);
    mem1 = fmaf(be1, mem1, syn1) * keep1;
    spk1 = (mem1 > 1.0f) ? 1.0f : 0.0f;
    const float keep2 = (mem2 > 1.0f) ? 0.0f : 1.0f;
    syn2 = fmaf(0.8f, syn2, spk1);
    mem2 = fmaf(0.9f, mem2, syn2) * keep2;
    spk2 = (mem2 > 1.0f) ? 1.0f : 0.0f;
}

// ---------------------------------------------------------------------------
// Kernel 1: cur1 = x @ W1^T + b1.  4 accumulators break the serial FMA chain
// (112 -> 28 deep). Also resets the chunk flags for the fused kernel (stream-
// ordered before it), keeping every launch's flag state identical.
// ---------------------------------------------------------------------------
#define KSPLIT 7
#define KPART (NIN / KSPLIT)           // 112 floats = 28 float4

__global__ void gemm_kernel(const float* __restrict__ x,
                            const float* __restrict__ W1,
                            const float* __restrict__ b1) {
    __shared__ float xs[NIN];
    __shared__ float partial[H][KSPLIT + 1];
    const int b = blockIdx.x;
    const int tid = threadIdx.x;

    if (b == 0 && tid < NCHUNK) g_flags[tid * 32] = 0;   // reset sync flags

    for (int k = tid; k < NIN; k += blockDim.x)
        xs[k] = x[b * NIN + k];
    __syncthreads();

    if (tid < H * KSPLIT) {
        const int h = tid % H;
        const int p = tid / H;
        const float4* w = reinterpret_cast<const float4*>(W1 + (size_t)h * NIN + p * KPART);
        const float* xp = xs + p * KPART;
        float a0 = 0.f, a1 = 0.f, a2 = 0.f, a3 = 0.f;
#pragma unroll
        for (int k4 = 0; k4 < KPART / 4; k4++) {
            float4 wv = w[k4];
            a0 = fmaf(xp[4 * k4 + 0], wv.x, a0);
            a1 = fmaf(xp[4 * k4 + 1], wv.y, a1);
            a2 = fmaf(xp[4 * k4 + 2], wv.z, a2);
            a3 = fmaf(xp[4 * k4 + 3], wv.w, a3);
        }
        partial[h][p] = (a0 + a1) + (a2 + a3);
    }
    __syncthreads();

    if (tid < H) {
        float s = b1[tid];
#pragma unroll
        for (int p = 0; p < KSPLIT; p++) s += partial[tid][p];
        g_cur1[b * H + tid] = s;
    }
}

// ---------------------------------------------------------------------------
// Fused kernel:
//   blocks [0, P1_BLOCKS): phase 1 — serial recurrence, checkpoint at each
//     chunk start, release flag[c] (threadfence + atomicAdd) BEFORE computing
//     the chunk, so consumers unblock as early as possible.
//   blocks [P1_BLOCKS, P1_BLOCKS+P2_BLOCKS): phase 2 — wait for flag[c],
//     replay CHUNK steps for 4 consecutive cells, float4 stores to all 5
//     sections (cur broadcast fused). DRAM-bound; phase 1 hides underneath.
// ---------------------------------------------------------------------------
__global__ void __launch_bounds__(128) snn_fused(const float* __restrict__ alpha1,
                                                 const float* __restrict__ beta1,
                                                 float* __restrict__ out) {
    const float a1  = fminf(fmaxf(alpha1[0], 0.0f), 1.0f);
    const float be1 = fminf(fmaxf(beta1[0], 0.0f), 1.0f);
    const int tid = threadIdx.x;

    if (blockIdx.x < P1_BLOCKS) {
        // ---------------- phase 1 ----------------
        const int cell = blockIdx.x * 128 + tid;
        const float cur = g_cur1[cell];
        float syn1 = 0.f, mem1 = 0.f, syn2 = 0.f, mem2 = 0.f;
        float spk1, spk2;

        for (int c = 0; c < NCHUNK; c++) {
            g_ckpt[c * BH + cell] = make_float4(syn1, mem1, syn2, mem2);
            __threadfence();
            __syncthreads();                       // whole block's ckpt written
            if (tid == 0) atomicAdd(&g_flags[c * 32], 1);
#pragma unroll 5
            for (int i = 0; i < CHUNK; i++)
                lif_step(a1, be1, cur, syn1, mem1, syn2, mem2, spk1, spk2);
        }
    } else {
        // ---------------- phase 2 ----------------
        const int idx = blockIdx.x - P1_BLOCKS;
        const int c = idx / P2_BLOCKS_PER_CHUNK;           // chunk-major order
        const int blk = idx % P2_BLOCKS_PER_CHUNK;
        const int cell0 = (blk * 128 + tid) * CELLS_PER_THREAD;

        if (tid == 0) {
            while (atomicAdd(&g_flags[c * 32], 0) < P1_BLOCKS)
                __nanosleep(200);
        }
        __syncthreads();
        __threadfence();

        const float4 cur4 = *reinterpret_cast<const float4*>(g_cur1 + cell0);
        float cur[4] = {cur4.x, cur4.y, cur4.z, cur4.w};

        float syn1[4], mem1[4], syn2[4], mem2[4], spk1[4], spk2[4];
#pragma unroll
        for (int j = 0; j < 4; j++) {
            float4 st = g_ckpt[c * BH + cell0 + j];
            syn1[j] = st.x; mem1[j] = st.y; syn2[j] = st.z; mem2[j] = st.w;
        }

        float* __restrict__ spk2o = out;
        float* __restrict__ mem2o = out + SEC;
        float* __restrict__ curo  = out + 2 * SEC;
        float* __restrict__ spk1o = out + 3 * SEC;
        float* __restrict__ mem1o = out + 4 * SEC;

        size_t off = (size_t)(c * CHUNK) * BH + cell0;
#pragma unroll 2
        for (int i = 0; i < CHUNK; i++, off += BH) {
#pragma unroll
            for (int j = 0; j < 4; j++)
                lif_step(a1, be1, cur[j], syn1[j], mem1[j], syn2[j], mem2[j],
                         spk1[j], spk2[j]);
            *reinterpret_cast<float4*>(spk2o + off) =
                make_float4(spk2[0], spk2[1], spk2[2], spk2[3]);
            *reinterpret_cast<float4*>(mem2o + off) =
                make_float4(mem2[0], mem2[1], mem2[2], mem2[3]);
            *reinterpret_cast<float4*>(curo + off) = cur4;
            *reinterpret_cast<float4*>(spk1o + off) =
                make_float4(spk1[0], spk1[1], spk1[2], spk1[3]);
            *reinterpret_cast<float4*>(mem1o + off) =
                make_float4(mem1[0], mem1[1], mem1[2], mem1[3]);
        }
    }
}

// ---------------------------------------------------------------------------
// Inputs: x[256*784], W1[100*784], b1[100], alpha1[1], beta1[1]  (all f32)
// Output: 5 sections of [T,B,H] f32: spk2, mem2, cur, spk1, mem1
// ---------------------------------------------------------------------------
extern "C" void kernel_launch(void* const* d_in, const int* in_sizes, int n_in,
                              void* d_out, int out_size) {
    const float* x      = (const float*)d_in[0];
    const float* W1     = (const float*)d_in[1];
    const float* b1     = (const float*)d_in[2];
    const float* alpha1 = (const float*)d_in[3];
    const float* beta1  = (const float*)d_in[4];
    float* out = (float*)d_out;

    gemm_kernel<<<BATCH, H * KSPLIT>>>(x, W1, b1);
    snn_fused<<<P1_BLOCKS + P2_BLOCKS, 128>>>(alpha1, beta1, out);
}